// round 16
// baseline (speedup 1.0000x reference)
#include <cuda_runtime.h>
#include <cuda_fp16.h>
#include <cstdint>
#include <cstddef>
#include <cmath>

#define HDIM    1024
#define GDIM    4096
#define BATCH   64
#define TSTEPS  256
#define NLAYERS 4
#define KC      128                // k elements per recurrence chunk
#define NCH     (HDIM / KC)        // 8
#define NFLAG   16                 // one readiness flag per 64-unit producer group

// ---- lstm smem layout (u32 words) ----
#define WP         516                       // W row stride in words (512 data + 4 pad)
#define W_WORDS    (32 * WP)                 // 16512
#define WBUF       768                       // per-warp A buffer: 64 rows * 12 words
#define WARP_REG   (3 * WBUF)                // 2304 words: 3 buffers, == reduction region
#define A_OFF      W_WORDS
#define RED_STRIDE 36                        // conflict-free, float2-aligned
#define RED_WARP   (64 * RED_STRIDE)         // 2304 == WARP_REG (exact alias per warp)
#define F_OFF      (A_OFF + 8 * WARP_REG)    // 34944
#define LSTM_WORDS (F_OFF + 16)              // 34960 words = 139840 B

// ---------------- scratch (static __device__ — allocation-free) ----------------
__device__ __align__(256) float    g_xp[(size_t)TSTEPS * BATCH * GDIM];     // fp32 xp
__device__ __align__(256) __half   g_hs16[(size_t)TSTEPS * BATCH * HDIM];   // fp16 h chain
__device__ __align__(256) __half   g_zero16[BATCH * HDIM];                  // zeros
__device__ __align__(256) uint32_t g_wih16[(size_t)(NLAYERS - 1) * GDIM * (HDIM / 2)]; // fp16x2 W_ih
__device__ int g_ck[NFLAG * 32];   // per-group monotonic counters, 128B apart

// ---------------- helpers ----------------
__device__ __forceinline__ void mma_f16(float c[4],
    uint32_t a0, uint32_t a1, uint32_t a2, uint32_t a3, uint32_t b0, uint32_t b1)
{
    asm volatile(
        "mma.sync.aligned.m16n8k16.row.col.f32.f16.f16.f32 "
        "{%0,%1,%2,%3}, {%4,%5,%6,%7}, {%8,%9}, {%0,%1,%2,%3};\n"
        : "+f"(c[0]), "+f"(c[1]), "+f"(c[2]), "+f"(c[3])
        : "r"(a0), "r"(a1), "r"(a2), "r"(a3), "r"(b0), "r"(b1));
}
__device__ __forceinline__ uint32_t smem_u32(const void* p) {
    return (uint32_t)__cvta_generic_to_shared(p);
}
__device__ __forceinline__ void cp16(uint32_t dst, const void* src) {
    asm volatile("cp.async.cg.shared.global [%0], [%1], 16;\n" :: "r"(dst), "l"(src));
}
#define CP_COMMIT() asm volatile("cp.async.commit_group;\n" ::: "memory")
#define CP_WAIT0()  asm volatile("cp.async.wait_group 0;\n" ::: "memory")
#define CP_WAIT1()  asm volatile("cp.async.wait_group 1;\n" ::: "memory")
#define BAR1()      asm volatile("bar.sync 1, 256;\n" ::: "memory")

__device__ __forceinline__ float sigf(float x) {
    return __fdividef(1.f, 1.f + __expf(-x));
}
__device__ __forceinline__ float tanhfast(float x) {
    return 1.f - __fdividef(2.f, __expf(2.f * x) + 1.f);
}
// release-add: orders all prior global stores before the increment
__device__ __forceinline__ void red_release_add(int* p) {
    asm volatile("red.release.gpu.global.add.s32 [%0], 1;" :: "l"(p) : "memory");
}

// ---------------------------------------------------------------------------
__global__ void reset_kernel() {
    if (threadIdx.x < NFLAG * 32) g_ck[threadIdx.x] = 0;
}
__global__ void zeroh_kernel() {
    reinterpret_cast<uint32_t*>(g_zero16)[blockIdx.x * 256 + threadIdx.x] = 0u;
}
// pre-convert W_ih (layers 1..3) fp32 -> fp16 pairs
__global__ void cvt_wih_kernel(const float* __restrict__ w) {
    const size_t i = (size_t)blockIdx.x * 256 + threadIdx.x;
    const float2 v = reinterpret_cast<const float2*>(w)[i];
    __half2 hp = __floats2half2_rn(v.x, v.y);
    g_wih16[i] = *reinterpret_cast<uint32_t*>(&hp);
}

// ---------------------------------------------------------------------------
// Layer-0 input projection (exact fp32, 2 MACs/output); launched twice (offset)
// ---------------------------------------------------------------------------
__global__ void layer0_xp_kernel(const float* __restrict__ x, const float* __restrict__ w0,
                                 const float* __restrict__ bih, const float* __restrict__ bhh,
                                 int off)
{
    const int idx = off + blockIdx.x * 256 + threadIdx.x;
    const int g = idx & (GDIM - 1);
    const int m = idx >> 12;
    const int t = m >> 6;
    const int b = m & 63;
    const float x0 = x[(b * TSTEPS + t) * 2 + 0];
    const float x1 = x[(b * TSTEPS + t) * 2 + 1];
    g_xp[idx] = x0 * w0[2 * g] + x1 * w0[2 * g + 1] + bih[g] + bhh[g];
}

// ---------------------------------------------------------------------------
// Input projection layers 1..3 (fp16 HMMA, unchanged — proven)
// ---------------------------------------------------------------------------
__global__ __launch_bounds__(256) void proj_kernel(
    int layer,
    const float* __restrict__ bih,
    const float* __restrict__ bhh)
{
    extern __shared__ uint32_t psh[];
    uint32_t* sA = psh;                 // 2 * 128*36
    uint32_t* sB = psh + 2 * 128 * 36;  // 2 * 64*36

    const uint32_t* wih16 = g_wih16 + (size_t)(layer - 1) * GDIM * (HDIM / 2);

    const int nb = blockIdx.x;
    const int mb = blockIdx.y;
    const __half* A  = g_hs16 + (size_t)mb * 128 * HDIM;
    const __half* Bm = reinterpret_cast<const __half*>(wih16) + (size_t)nb * 64 * HDIM;

    const int tid  = threadIdx.x, lane = tid & 31, wp = tid >> 5;
    const int mrow = (wp >> 1) * 32;
    const int nbase = (wp & 1) * 32;
    const int gid = lane >> 2, tig = lane & 3;

    const int arow = tid >> 1, asub = tid & 1;
    const int brow = tid >> 2, bsub = tid & 3;
    const uint32_t sAa = smem_u32(sA), sBa = smem_u32(sB);

    auto issue = [&](int ch) {
        const int bi = ch & 1;
        const __half* as = A + (size_t)arow * HDIM + ch * 64 + asub * 32;
        uint32_t ad = sAa + (uint32_t)(bi * 128 * 36 + arow * 36 + asub * 16) * 4;
        #pragma unroll
        for (int i = 0; i < 4; i++) cp16(ad + i * 16, as + i * 8);
        const __half* bs = Bm + (size_t)brow * HDIM + ch * 64 + bsub * 16;
        uint32_t bd = sBa + (uint32_t)(bi * 64 * 36 + brow * 36 + bsub * 8) * 4;
        #pragma unroll
        for (int i = 0; i < 2; i++) cp16(bd + i * 16, bs + i * 8);
        CP_COMMIT();
    };

    issue(0); issue(1);
    float acc[2][4][4] = {};

    for (int ch = 0; ch < 16; ch++) {
        if (ch >= 14) { CP_WAIT0(); } else { CP_WAIT1(); }
        __syncthreads();
        const uint32_t* bufA = sA + (ch & 1) * 128 * 36;
        const uint32_t* bufB = sB + (ch & 1) * 64 * 36;
        #pragma unroll
        for (int ks = 0; ks < 4; ks++) {
            const int kw = ks * 8 + tig;
            uint32_t a[2][4];
            #pragma unroll
            for (int mh = 0; mh < 2; mh++) {
                const int r = mrow + mh * 16 + gid;
                a[mh][0] = bufA[r * 36 + kw];
                a[mh][1] = bufA[(r + 8) * 36 + kw];
                a[mh][2] = bufA[r * 36 + kw + 4];
                a[mh][3] = bufA[(r + 8) * 36 + kw + 4];
            }
            #pragma unroll
            for (int nt = 0; nt < 4; nt++) {
                const int br = nbase + nt * 8 + gid;
                uint32_t b0 = bufB[br * 36 + kw];
                uint32_t b1 = bufB[br * 36 + kw + 4];
                mma_f16(acc[0][nt], a[0][0], a[0][1], a[0][2], a[0][3], b0, b1);
                mma_f16(acc[1][nt], a[1][0], a[1][1], a[1][2], a[1][3], b0, b1);
            }
        }
        __syncthreads();
        if (ch + 2 < 16) issue(ch + 2);
    }

    #pragma unroll
    for (int mh = 0; mh < 2; mh++) {
        #pragma unroll
        for (int nt = 0; nt < 4; nt++) {
            const int c = nbase + nt * 8 + tig * 2;
            const int n = nb * 64 + c;
            const float b0v = bih[n] + bhh[n];
            const float b1v = bih[n + 1] + bhh[n + 1];
            const int r0 = mrow + mh * 16 + gid, r1 = r0 + 8;
            float* o0 = g_xp + ((size_t)mb * 128 + r0) * GDIM + n;
            float* o1 = g_xp + ((size_t)mb * 128 + r1) * GDIM + n;
            o0[0] = acc[mh][nt][0] + b0v;
            o0[1] = acc[mh][nt][1] + b1v;
            o1[0] = acc[mh][nt][2] + b0v;
            o1[1] = acc[mh][nt][3] + b1v;
        }
    }
}

// ---------------------------------------------------------------------------
// Persistent LSTM layer kernel — fp16 HMMA, WARP-PRIVATE A pipelines:
// each warp copies only its own 16-k-column slice (triple-buffered, stride 12
// -> aligned + conflict-free), so the 8-chunk loop has ZERO barriers; the
// warp's partial-reduction region aliases exactly its own A buffers. Only 2
// bar.sync per step (around the cross-warp reduction). Rotated chunk order.
// 128 CTAs x 288 threads: warps 0-7 compute, warp 8 polls producer flags.
// ---------------------------------------------------------------------------
__global__ __launch_bounds__(288, 1) void lstm_layer_kernel(
    const float* __restrict__ whh, int step_base)
{
    extern __shared__ uint32_t sh[];
    uint32_t* sW = sh;                       // [32][WP] fp16 pairs
    uint32_t* sA = sh + A_OFF;               // 8 warp regions (A bufs == sR alias)
    volatile int* sF = (volatile int*)(sh + F_OFF);

    const int tid = threadIdx.x;
    const int u   = blockIdx.x;              // 0..127

    // --- one-time init: W rows [i0..7,f0..7,g0..7,o0..7] as fp16 pairs ---
    if (tid < 256) {
        for (int idx = tid; idx < 32 * 512; idx += 256) {
            const int r = idx >> 9, wd = idx & 511;
            const int tau = r >> 3, j = r & 7;
            const float2 v = *reinterpret_cast<const float2*>(
                whh + ((size_t)(tau * HDIM + u * 8 + j)) * HDIM + wd * 2);
            __half2 hp = __floats2half2_rn(v.x, v.y);
            sW[r * WP + wd] = *reinterpret_cast<uint32_t*>(&hp);
        }
    } else if (tid - 256 < NFLAG) {
        sF[tid - 256] = 0;
    }
    __syncthreads();

    // ---------------- poll warp ----------------
    if (tid >= 256) {
        const int c = tid - 256;
        if (c < NFLAG) {
            volatile int* ctr = &g_ck[c * 32];
            for (int p = 1; p < TSTEPS; p++) {
                const int tgt = 8 * (step_base + p);
                while (*ctr < tgt) __nanosleep(16);
                sF[c] = p;
            }
        }
        return;
    }

    // ---------------- compute warps ----------------
    const int lane = tid & 31, wid = tid >> 5;
    const int gid = lane >> 2, tig = lane & 3;

    // warp-private A region: 3 buffers of 768 words (64 rows * 12)
    uint32_t* wreg = sA + wid * WARP_REG;
    const uint32_t wrega = smem_u32(wreg);

    // copy mapping: lane covers rows 2*lane, 2*lane+1; 2 cp16 per row
    const int row0 = lane * 2;

    const int eb = tid >> 2;            // epilogue batch 0..63
    const int jp = tid & 3;             // epilogue unit pair 0..3

    const int c0 = u >> 4;              // rotated start: this CTA's own chunk

    float cs0 = 0.f, cs1 = 0.f;         // cell state (2 units) in registers

    for (int t = 0; t < TSTEPS; t++) {
        const __half* h_prev = t ? (g_hs16 + (size_t)(t - 1) * (BATCH * HDIM)) : g_zero16;
        const float*  xp_t   = g_xp + (size_t)t * (BATCH * GDIM);

        // xp for this thread's (batch, unit pair): 4 gate pairs (fp32)
        float2 xv[4];
        {
            const float* xb = xp_t + (size_t)eb * GDIM + u * 8 + jp * 2;
            #pragma unroll
            for (int tau = 0; tau < 4; tau++)
                xv[tau] = *(const float2*)(xb + tau * HDIM);
        }

        auto waitF = [&](int ch) {
            const int f = 2 * ch;
            while (sF[f] < t || sF[f + 1] < t) { }
        };
        // copy this warp's 16-k-column slice of chunk ch into buffer bi
        auto issueA = [&](int ch, int bi) {
            const __half* s0 = h_prev + (size_t)row0 * HDIM + ch * KC + wid * 16;
            uint32_t d0 = wrega + (uint32_t)(bi * WBUF + row0 * 12) * 4;
            cp16(d0,            s0);
            cp16(d0 + 16,       s0 + 8);
            cp16(d0 + 48,       s0 + HDIM);
            cp16(d0 + 64,       s0 + HDIM + 8);
            CP_COMMIT();
        };

        // prologue: first two chunks in rotated order (warp-local)
        waitF(c0);            issueA(c0, 0);
        waitF((c0 + 1) & 7);  issueA((c0 + 1) & 7, 1);

        float acc[4][4][4] = {};

        #pragma unroll 1
        for (int i = 0; i < NCH; i++) {
            if (i < NCH - 1) { CP_WAIT1(); } else { CP_WAIT0(); }
            if (i + 2 < NCH) {
                const int chn = (c0 + i + 2) & 7;
                waitF(chn);
                issueA(chn, (i + 2) % 3);
            }
            const int ch = (c0 + i) & 7;
            const uint32_t* buf = wreg + (i % 3) * WBUF;
            const uint32_t* wb  = sW + ch * 64 + wid * 8;   // this warp's k-slice
            uint32_t bf[4][2];
            #pragma unroll
            for (int nt = 0; nt < 4; nt++) {
                bf[nt][0] = wb[(nt * 8 + gid) * WP + tig];
                bf[nt][1] = wb[(nt * 8 + gid) * WP + tig + 4];
            }
            #pragma unroll
            for (int mt = 0; mt < 4; mt++) {
                const int r = mt * 16 + gid;
                uint32_t a0 = buf[r * 12 + tig];
                uint32_t a1 = buf[(r + 8) * 12 + tig];
                uint32_t a2 = buf[r * 12 + tig + 4];
                uint32_t a3 = buf[(r + 8) * 12 + tig + 4];
                #pragma unroll
                for (int nt = 0; nt < 4; nt++)
                    mma_f16(acc[mt][nt], a0, a1, a2, a3, bf[nt][0], bf[nt][1]);
            }
        }

        // ---- write partials into OWN region (aliases own dead A buffers) ----
        float* sR = (float*)sA;
        {
            float* base = sR + wid * RED_WARP;
            #pragma unroll
            for (int mt = 0; mt < 4; mt++) {
                const int r = mt * 16 + gid;
                #pragma unroll
                for (int nt = 0; nt < 4; nt++) {
                    const int c = nt * 8 + tig * 2;
                    *(float2*)&base[r * RED_STRIDE + c] =
                        make_float2(acc[mt][nt][0], acc[mt][nt][1]);
                    *(float2*)&base[(r + 8) * RED_STRIDE + c] =
                        make_float2(acc[mt][nt][2], acc[mt][nt][3]);
                }
            }
        }
        BAR1();   // partials of all warps visible

        // ---- reduce partials + gate math + cell update (2 units/thread) ----
        {
            float2 gs[4];
            #pragma unroll
            for (int tau = 0; tau < 4; tau++) gs[tau] = make_float2(0.f, 0.f);
            #pragma unroll
            for (int w = 0; w < 8; w++) {
                const float* p = sR + w * RED_WARP + eb * RED_STRIDE + jp * 2;
                #pragma unroll
                for (int tau = 0; tau < 4; tau++) {
                    float2 v = *(const float2*)(p + tau * 8);
                    gs[tau].x += v.x; gs[tau].y += v.y;
                }
            }
            const float i0 = sigf(gs[0].x + xv[0].x), i1 = sigf(gs[0].y + xv[0].y);
            const float f0 = sigf(gs[1].x + xv[1].x), f1 = sigf(gs[1].y + xv[1].y);
            const float q0 = tanhfast(gs[2].x + xv[2].x), q1 = tanhfast(gs[2].y + xv[2].y);
            const float o0 = sigf(gs[3].x + xv[3].x), o1 = sigf(gs[3].y + xv[3].y);
            cs0 = f0 * cs0 + i0 * q0;
            cs1 = f1 * cs1 + i1 * q1;
            __half2 hp = __floats2half2_rn(o0 * tanhfast(cs0), o1 * tanhfast(cs1));
            *reinterpret_cast<uint32_t*>(
                g_hs16 + (size_t)t * (BATCH * HDIM) + (size_t)eb * HDIM + u * 8 + jp * 2) =
                *reinterpret_cast<uint32_t*>(&hp);
        }

        // all sR reads + h stores done -> release this CTA's group counter
        BAR1();
        if (tid == 0) red_release_add(&g_ck[(u >> 3) * 32]);
    }
}

// ---------------------------------------------------------------------------
__global__ void fc_kernel(const float* __restrict__ fc_w, const float* __restrict__ fc_b,
                          float* __restrict__ out)
{
    const int b = blockIdx.x;
    const __half* h = g_hs16 + (size_t)(TSTEPS - 1) * (BATCH * HDIM) + (size_t)b * HDIM;
    float s = 0.f;
    for (int k = threadIdx.x; k < HDIM; k += 256) s += __half2float(h[k]) * fc_w[k];
    #pragma unroll
    for (int o = 16; o > 0; o >>= 1) s += __shfl_down_sync(0xffffffffu, s, o);
    __shared__ float red[8];
    if ((threadIdx.x & 31) == 0) red[threadIdx.x >> 5] = s;
    __syncthreads();
    if (threadIdx.x == 0) {
        float v = 0.f;
        #pragma unroll
        for (int i = 0; i < 8; i++) v += red[i];
        out[b] = v + fc_b[0];
    }
}

// ---------------------------------------------------------------------------
extern "C" void kernel_launch(void* const* d_in, const int* in_sizes, int n_in,
                              void* d_out, int out_size)
{
    (void)in_sizes; (void)n_in; (void)out_size;
    const float* x      = (const float*)d_in[0];
    const float* w_ih0  = (const float*)d_in[1];
    const float* w_rest = (const float*)d_in[2];
    const float* w_hh   = (const float*)d_in[3];
    const float* b_ih   = (const float*)d_in[4];
    const float* b_hh   = (const float*)d_in[5];
    const float* fc_w   = (const float*)d_in[6];
    const float* fc_b   = (const float*)d_in[7];
    float* out = (float*)d_out;

    const int lstm_smem = LSTM_WORDS * 4;                    // 139,840 B
    const int proj_smem = (2 * 128 * 36 + 2 * 64 * 36) * 4;  // 55,296 B
    static bool attr_set = false;
    if (!attr_set) {
        cudaFuncSetAttribute(lstm_layer_kernel,
                             cudaFuncAttributeMaxDynamicSharedMemorySize, lstm_smem);
        cudaFuncSetAttribute(proj_kernel,
                             cudaFuncAttributeMaxDynamicSharedMemorySize, proj_smem);
        attr_set = true;
    }

    const int half_l0 = (TSTEPS * BATCH * GDIM) / 2;

    reset_kernel<<<1, NFLAG * 32>>>();                                   // 0
    zeroh_kernel<<<(BATCH * HDIM / 2) / 256, 256>>>();                   // 1
    cvt_wih_kernel<<<(int)(((size_t)(NLAYERS - 1) * GDIM * HDIM / 2) / 256), 256>>>(w_rest); // 2
    layer0_xp_kernel<<<half_l0 / 256, 256>>>(x, w_ih0, b_ih, b_hh, 0);          // 3
    layer0_xp_kernel<<<half_l0 / 256, 256>>>(x, w_ih0, b_ih, b_hh, half_l0);    // 4

    for (int l = 0; l < NLAYERS; l++) {
        if (l > 0) {
            proj_kernel<<<dim3(64, 128), 256, proj_smem>>>(
                l,
                b_ih + (size_t)l * GDIM,
                b_hh + (size_t)l * GDIM);
        }
        lstm_layer_kernel<<<128, 288, lstm_smem>>>(                      // lstm0 at slot 5
            w_hh + (size_t)l * GDIM * HDIM, l * TSTEPS);
    }

    fc_kernel<<<BATCH, 256>>>(fc_w, fc_b, out);
}

// round 17
// speedup vs baseline: 1.0665x; 1.0665x over previous
#include <cuda_runtime.h>
#include <cuda_fp16.h>
#include <cstdint>
#include <cstddef>
#include <cmath>

#define HDIM    1024
#define GDIM    4096
#define BATCH   64
#define TSTEPS  256
#define NLAYERS 4
#define KC      128                // k elements per recurrence chunk
#define NCH     (HDIM / KC)        // 8
#define NFLAG   16                 // one readiness flag per 64-unit producer group

// ---- lstm smem layout (u32 words) ----
#define WP         516                       // W row stride in words (512 data + 4 pad)
#define W_WORDS    (32 * WP)                 // 16512
#define WI_OFF     W_WORDS                   // W_ih (next layer) rows
#define A_OFF      (2 * W_WORDS)             // 33024: A buffers / reduction alias
#define ABUF_WORDS (64 * 68)                 // 4352
#define RED_STRIDE 36                        // conflict-free, float2-aligned
#define RED_WARP   (64 * RED_STRIDE)         // 2304
#define RED_WORDS  (8 * RED_WARP)            // 18432 (covers 3 A buffers = 13056)
#define F_OFF      (A_OFF + RED_WORDS)       // 51456
#define LSTM_WORDS (F_OFF + 16)              // 51472 words = 205888 B

// ---------------- scratch (static __device__ — allocation-free) ----------------
__device__ __align__(256) float    g_xp[(size_t)TSTEPS * BATCH * GDIM];     // fp32 xp (no bias)
__device__ __align__(256) __half   g_hs16[(size_t)TSTEPS * BATCH * HDIM];   // fp16 h chain
__device__ __align__(256) __half   g_zero16[BATCH * HDIM];                  // zeros
__device__ __align__(256) uint32_t g_wih16[(size_t)(NLAYERS - 1) * GDIM * (HDIM / 2)]; // fp16x2 W_ih
__device__ int g_ck[NFLAG * 32];   // per-group monotonic counters, 128B apart

// ---------------- helpers ----------------
__device__ __forceinline__ void mma_f16(float c[4],
    uint32_t a0, uint32_t a1, uint32_t a2, uint32_t a3, uint32_t b0, uint32_t b1)
{
    asm volatile(
        "mma.sync.aligned.m16n8k16.row.col.f32.f16.f16.f32 "
        "{%0,%1,%2,%3}, {%4,%5,%6,%7}, {%8,%9}, {%0,%1,%2,%3};\n"
        : "+f"(c[0]), "+f"(c[1]), "+f"(c[2]), "+f"(c[3])
        : "r"(a0), "r"(a1), "r"(a2), "r"(a3), "r"(b0), "r"(b1));
}
__device__ __forceinline__ uint32_t smem_u32(const void* p) {
    return (uint32_t)__cvta_generic_to_shared(p);
}
__device__ __forceinline__ void cp16(uint32_t dst, const void* src) {
    asm volatile("cp.async.cg.shared.global [%0], [%1], 16;\n" :: "r"(dst), "l"(src));
}
#define CP_COMMIT() asm volatile("cp.async.commit_group;\n" ::: "memory")
#define CP_WAIT0()  asm volatile("cp.async.wait_group 0;\n" ::: "memory")
#define CP_WAIT1()  asm volatile("cp.async.wait_group 1;\n" ::: "memory")
#define BAR1()      asm volatile("bar.sync 1, 256;\n" ::: "memory")

__device__ __forceinline__ float sigf(float x) {
    return __fdividef(1.f, 1.f + __expf(-x));
}
__device__ __forceinline__ float tanhfast(float x) {
    return 1.f - __fdividef(2.f, __expf(2.f * x) + 1.f);
}
__device__ __forceinline__ void red_release_add(int* p) {
    asm volatile("red.release.gpu.global.add.s32 [%0], 1;" :: "l"(p) : "memory");
}

// ---------------------------------------------------------------------------
__global__ void reset_kernel() {
    if (threadIdx.x < NFLAG * 32) g_ck[threadIdx.x] = 0;
}
__global__ void zeroh_kernel() {
    reinterpret_cast<uint32_t*>(g_zero16)[blockIdx.x * 256 + threadIdx.x] = 0u;
}
// pre-convert W_ih (layers 1..3) fp32 -> fp16 pairs
__global__ void cvt_wih_kernel(const float* __restrict__ w) {
    const size_t i = (size_t)blockIdx.x * 256 + threadIdx.x;
    const float2 v = reinterpret_cast<const float2*>(w)[i];
    __half2 hp = __floats2half2_rn(v.x, v.y);
    g_wih16[i] = *reinterpret_cast<uint32_t*>(&hp);
}

// ---------------------------------------------------------------------------
// Layer-0 input projection (exact fp32, 2 MACs/output, NO bias — bias is
// added in the lstm epilogue uniformly for all layers); launched twice.
// ---------------------------------------------------------------------------
__global__ void layer0_xp_kernel(const float* __restrict__ x, const float* __restrict__ w0,
                                 int off)
{
    const int idx = off + blockIdx.x * 256 + threadIdx.x;
    const int g = idx & (GDIM - 1);
    const int m = idx >> 12;
    const int t = m >> 6;
    const int b = m & 63;
    const float x0 = x[(b * TSTEPS + t) * 2 + 0];
    const float x1 = x[(b * TSTEPS + t) * 2 + 1];
    g_xp[idx] = x0 * w0[2 * g] + x1 * w0[2 * g + 1];
}

// ---------------------------------------------------------------------------
// Persistent LSTM layer kernel with FUSED next-layer input projection.
// Per step t: recurrence GEMM on h[t-1] (critical path) + proj GEMM
// xp_{l+1}[t-1] = h[t-1] @ W_ih_{l+1}^T on the SAME staged A data (off
// critical path, epilogue phase 2 trails the h release). Trailing pass
// computes xp[T-1]. R14 pipeline otherwise: rotated chunk order, triple
// buffers, stride-36 reduction, release-add, poll warp (now to p=T).
// ---------------------------------------------------------------------------
template<bool DOPROJ>
__global__ __launch_bounds__(288, 1) void lstm_layer_kernel(
    const float* __restrict__ whh, int step_base, int nl,
    const float* __restrict__ bih, const float* __restrict__ bhh)
{
    extern __shared__ uint32_t sh[];
    uint32_t* sW  = sh;                      // [32][WP] W_hh fp16 pairs
    uint32_t* sWI = sh + WI_OFF;             // [32][WP] W_ih(next) fp16 pairs
    uint32_t* sA  = sh + A_OFF;              // 3 A buffers [64][68] (alias sR)
    volatile int* sF = (volatile int*)(sh + F_OFF);

    const int tid = threadIdx.x;
    const int u   = blockIdx.x;              // 0..127

    // --- one-time init ---
    if (tid < 256) {
        for (int idx = tid; idx < 32 * 512; idx += 256) {
            const int r = idx >> 9, wd = idx & 511;
            const int tau = r >> 3, j = r & 7;
            const float2 v = *reinterpret_cast<const float2*>(
                whh + ((size_t)(tau * HDIM + u * 8 + j)) * HDIM + wd * 2);
            __half2 hp = __floats2half2_rn(v.x, v.y);
            sW[r * WP + wd] = *reinterpret_cast<uint32_t*>(&hp);
        }
        if (DOPROJ) {
            const uint32_t* wih = g_wih16 + (size_t)nl * GDIM * 512;
            for (int idx = tid; idx < 32 * 512; idx += 256) {
                const int r = idx >> 9, wd = idx & 511;
                const int tau = r >> 3, j = r & 7;
                sWI[r * WP + wd] = wih[(size_t)(tau * HDIM + u * 8 + j) * 512 + wd];
            }
        }
    } else if (tid - 256 < NFLAG) {
        sF[tid - 256] = 0;
    }
    __syncthreads();

    // ---------------- poll warp ----------------
    if (tid >= 256) {
        const int c = tid - 256;
        if (c < NFLAG) {
            volatile int* ctr = &g_ck[c * 32];
            for (int p = 1; p <= TSTEPS; p++) {
                const int tgt = 8 * (step_base + p);
                while (*ctr < tgt) __nanosleep(16);
                sF[c] = p;
            }
        }
        return;
    }

    // ---------------- compute warps ----------------
    const int lane = tid & 31, wid = tid >> 5;
    const int gid = lane >> 2, tig = lane & 3;

    const int cr = tid >> 2;            // copy row 0..63
    const int cq = tid & 3;             // copy quad (32 halves = 64B each)
    const uint32_t sAa = smem_u32(sA);

    const int eb = tid >> 2;            // epilogue batch 0..63
    const int jp = tid & 3;             // epilogue unit pair 0..3

    const int c0 = u >> 4;              // rotated start: this CTA's own chunk

    // bias for this thread's unit pair (all 4 gates), fp32
    float2 bv[4];
    #pragma unroll
    for (int tau = 0; tau < 4; tau++) {
        const int n = tau * HDIM + u * 8 + jp * 2;
        bv[tau] = make_float2(bih[n] + bhh[n], bih[n + 1] + bhh[n + 1]);
    }

    float cs0 = 0.f, cs1 = 0.f;         // cell state (2 units) in registers
    float* sR = (float*)sA;

    auto issueA = [&](const __half* hbase, int ch, int bi) {
        const __half* src = hbase + (size_t)cr * HDIM + ch * KC + cq * 32;
        uint32_t dst = sAa + (uint32_t)(bi * ABUF_WORDS + cr * 68 + cq * 16) * 4;
        #pragma unroll
        for (int i = 0; i < 4; i++) cp16(dst + i * 16, src + i * 8);
        CP_COMMIT();
    };

    for (int t = 0; t < TSTEPS; t++) {
        const __half* h_prev = t ? (g_hs16 + (size_t)(t - 1) * (BATCH * HDIM)) : g_zero16;
        const float*  xp_t   = g_xp + (size_t)t * (BATCH * GDIM);

        // xp for this thread's (batch, unit pair): 4 gate pairs (fp32, no bias)
        float2 xv[4];
        {
            const float* xb = xp_t + (size_t)eb * GDIM + u * 8 + jp * 2;
            #pragma unroll
            for (int tau = 0; tau < 4; tau++)
                xv[tau] = *(const float2*)(xb + tau * HDIM);
        }

        auto waitF = [&](int ch) {
            const int f = 2 * ch;
            while (sF[f] < t || sF[f + 1] < t) { }
        };

        waitF(c0);            issueA(h_prev, c0, 0);
        waitF((c0 + 1) & 7);  issueA(h_prev, (c0 + 1) & 7, 1);

        float acc[4][4][4] = {};
        float accp[4][4][4] = {};

        #pragma unroll 1
        for (int i = 0; i < NCH; i++) {
            if (i < NCH - 1) { CP_WAIT1(); } else { CP_WAIT0(); }
            BAR1();   // copy(i) visible; compute(i-1) done by all
            if (i + 2 < NCH) {
                const int chn = (c0 + i + 2) & 7;
                waitF(chn);
                issueA(h_prev, chn, (i + 2) % 3);
            }
            const int ch = (c0 + i) & 7;
            const uint32_t* buf = sA + (i % 3) * ABUF_WORDS;
            const uint32_t* wbh = sW  + ch * 64 + wid * 8;
            const uint32_t* wbi = sWI + ch * 64 + wid * 8;
            const int kw = wid * 8 + tig;
            uint32_t bfh[4][2], bfi[4][2];
            #pragma unroll
            for (int nt = 0; nt < 4; nt++) {
                bfh[nt][0] = wbh[(nt * 8 + gid) * WP + tig];
                bfh[nt][1] = wbh[(nt * 8 + gid) * WP + tig + 4];
                if (DOPROJ) {
                    bfi[nt][0] = wbi[(nt * 8 + gid) * WP + tig];
                    bfi[nt][1] = wbi[(nt * 8 + gid) * WP + tig + 4];
                }
            }
            #pragma unroll
            for (int mt = 0; mt < 4; mt++) {
                const int r = mt * 16 + gid;
                uint32_t a0 = buf[r * 68 + kw];
                uint32_t a1 = buf[(r + 8) * 68 + kw];
                uint32_t a2 = buf[r * 68 + kw + 4];
                uint32_t a3 = buf[(r + 8) * 68 + kw + 4];
                #pragma unroll
                for (int nt = 0; nt < 4; nt++)
                    mma_f16(acc[mt][nt], a0, a1, a2, a3, bfh[nt][0], bfh[nt][1]);
                if (DOPROJ) {
                    #pragma unroll
                    for (int nt = 0; nt < 4; nt++)
                        mma_f16(accp[mt][nt], a0, a1, a2, a3, bfi[nt][0], bfi[nt][1]);
                }
            }
        }
        BAR1();   // all compute done -> safe to clobber sA with partials

        // ---- phase 1: recurrence partials, reduce, gate math, h store ----
        {
            float* base = sR + wid * RED_WARP;
            #pragma unroll
            for (int mt = 0; mt < 4; mt++) {
                const int r = mt * 16 + gid;
                #pragma unroll
                for (int nt = 0; nt < 4; nt++) {
                    const int c = nt * 8 + tig * 2;
                    *(float2*)&base[r * RED_STRIDE + c] =
                        make_float2(acc[mt][nt][0], acc[mt][nt][1]);
                    *(float2*)&base[(r + 8) * RED_STRIDE + c] =
                        make_float2(acc[mt][nt][2], acc[mt][nt][3]);
                }
            }
        }
        BAR1();
        {
            float2 gs[4];
            #pragma unroll
            for (int tau = 0; tau < 4; tau++) gs[tau] = make_float2(0.f, 0.f);
            #pragma unroll
            for (int w = 0; w < 8; w++) {
                const float* p = sR + w * RED_WARP + eb * RED_STRIDE + jp * 2;
                #pragma unroll
                for (int tau = 0; tau < 4; tau++) {
                    float2 v = *(const float2*)(p + tau * 8);
                    gs[tau].x += v.x; gs[tau].y += v.y;
                }
            }
            const float i0 = sigf(gs[0].x + xv[0].x + bv[0].x);
            const float i1 = sigf(gs[0].y + xv[0].y + bv[0].y);
            const float f0 = sigf(gs[1].x + xv[1].x + bv[1].x);
            const float f1 = sigf(gs[1].y + xv[1].y + bv[1].y);
            const float q0 = tanhfast(gs[2].x + xv[2].x + bv[2].x);
            const float q1 = tanhfast(gs[2].y + xv[2].y + bv[2].y);
            const float o0 = sigf(gs[3].x + xv[3].x + bv[3].x);
            const float o1 = sigf(gs[3].y + xv[3].y + bv[3].y);
            cs0 = f0 * cs0 + i0 * q0;
            cs1 = f1 * cs1 + i1 * q1;
            __half2 hp = __floats2half2_rn(o0 * tanhfast(cs0), o1 * tanhfast(cs1));
            *reinterpret_cast<uint32_t*>(
                g_hs16 + (size_t)t * (BATCH * HDIM) + (size_t)eb * HDIM + u * 8 + jp * 2) =
                *reinterpret_cast<uint32_t*>(&hp);
        }
        BAR1();   // h stores + phase-1 sR reads done
        if (tid == 0) red_release_add(&g_ck[(u >> 3) * 32]);   // CRITICAL PATH ENDS

        // ---- phase 2 (trailing): proj partials, reduce, store xp[t-1] ----
        if (DOPROJ && t > 0) {
            float* base = sR + wid * RED_WARP;
            #pragma unroll
            for (int mt = 0; mt < 4; mt++) {
                const int r = mt * 16 + gid;
                #pragma unroll
                for (int nt = 0; nt < 4; nt++) {
                    const int c = nt * 8 + tig * 2;
                    *(float2*)&base[r * RED_STRIDE + c] =
                        make_float2(accp[mt][nt][0], accp[mt][nt][1]);
                    *(float2*)&base[(r + 8) * RED_STRIDE + c] =
                        make_float2(accp[mt][nt][2], accp[mt][nt][3]);
                }
            }
            BAR1();
            float2 gp[4];
            #pragma unroll
            for (int tau = 0; tau < 4; tau++) gp[tau] = make_float2(0.f, 0.f);
            #pragma unroll
            for (int w = 0; w < 8; w++) {
                const float* p = sR + w * RED_WARP + eb * RED_STRIDE + jp * 2;
                #pragma unroll
                for (int tau = 0; tau < 4; tau++) {
                    float2 v = *(const float2*)(p + tau * 8);
                    gp[tau].x += v.x; gp[tau].y += v.y;
                }
            }
            float* xo = g_xp + (size_t)(t - 1) * (BATCH * GDIM) + (size_t)eb * GDIM + u * 8 + jp * 2;
            #pragma unroll
            for (int tau = 0; tau < 4; tau++)
                *(float2*)(xo + tau * HDIM) = gp[tau];
            BAR1();   // phase-2 sR reads done before next step's copies
        }
    }

    // ---- trailing pass: xp[T-1] from h[T-1] (DOPROJ only) ----
    if (DOPROJ) {
        const __half* hl = g_hs16 + (size_t)(TSTEPS - 1) * (BATCH * HDIM);
        auto waitT = [&](int ch) {
            const int f = 2 * ch;
            while (sF[f] < TSTEPS || sF[f + 1] < TSTEPS) { }
        };
        waitT(c0);            issueA(hl, c0, 0);
        waitT((c0 + 1) & 7);  issueA(hl, (c0 + 1) & 7, 1);

        float accp[4][4][4] = {};
        #pragma unroll 1
        for (int i = 0; i < NCH; i++) {
            if (i < NCH - 1) { CP_WAIT1(); } else { CP_WAIT0(); }
            BAR1();
            if (i + 2 < NCH) {
                const int chn = (c0 + i + 2) & 7;
                waitT(chn);
                issueA(hl, chn, (i + 2) % 3);
            }
            const int ch = (c0 + i) & 7;
            const uint32_t* buf = sA + (i % 3) * ABUF_WORDS;
            const uint32_t* wbi = sWI + ch * 64 + wid * 8;
            const int kw = wid * 8 + tig;
            uint32_t bfi[4][2];
            #pragma unroll
            for (int nt = 0; nt < 4; nt++) {
                bfi[nt][0] = wbi[(nt * 8 + gid) * WP + tig];
                bfi[nt][1] = wbi[(nt * 8 + gid) * WP + tig + 4];
            }
            #pragma unroll
            for (int mt = 0; mt < 4; mt++) {
                const int r = mt * 16 + gid;
                uint32_t a0 = buf[r * 68 + kw];
                uint32_t a1 = buf[(r + 8) * 68 + kw];
                uint32_t a2 = buf[r * 68 + kw + 4];
                uint32_t a3 = buf[(r + 8) * 68 + kw + 4];
                #pragma unroll
                for (int nt = 0; nt < 4; nt++)
                    mma_f16(accp[mt][nt], a0, a1, a2, a3, bfi[nt][0], bfi[nt][1]);
            }
        }
        BAR1();
        {
            float* base = sR + wid * RED_WARP;
            #pragma unroll
            for (int mt = 0; mt < 4; mt++) {
                const int r = mt * 16 + gid;
                #pragma unroll
                for (int nt = 0; nt < 4; nt++) {
                    const int c = nt * 8 + tig * 2;
                    *(float2*)&base[r * RED_STRIDE + c] =
                        make_float2(accp[mt][nt][0], accp[mt][nt][1]);
                    *(float2*)&base[(r + 8) * RED_STRIDE + c] =
                        make_float2(accp[mt][nt][2], accp[mt][nt][3]);
                }
            }
        }
        BAR1();
        {
            float2 gp[4];
            #pragma unroll
            for (int tau = 0; tau < 4; tau++) gp[tau] = make_float2(0.f, 0.f);
            #pragma unroll
            for (int w = 0; w < 8; w++) {
                const float* p = sR + w * RED_WARP + eb * RED_STRIDE + jp * 2;
                #pragma unroll
                for (int tau = 0; tau < 4; tau++) {
                    float2 v = *(const float2*)(p + tau * 8);
                    gp[tau].x += v.x; gp[tau].y += v.y;
                }
            }
            float* xo = g_xp + (size_t)(TSTEPS - 1) * (BATCH * GDIM) + (size_t)eb * GDIM + u * 8 + jp * 2;
            #pragma unroll
            for (int tau = 0; tau < 4; tau++)
                *(float2*)(xo + tau * HDIM) = gp[tau];
        }
    }
}

// ---------------------------------------------------------------------------
__global__ void fc_kernel(const float* __restrict__ fc_w, const float* __restrict__ fc_b,
                          float* __restrict__ out)
{
    const int b = blockIdx.x;
    const __half* h = g_hs16 + (size_t)(TSTEPS - 1) * (BATCH * HDIM) + (size_t)b * HDIM;
    float s = 0.f;
    for (int k = threadIdx.x; k < HDIM; k += 256) s += __half2float(h[k]) * fc_w[k];
    #pragma unroll
    for (int o = 16; o > 0; o >>= 1) s += __shfl_down_sync(0xffffffffu, s, o);
    __shared__ float red[8];
    if ((threadIdx.x & 31) == 0) red[threadIdx.x >> 5] = s;
    __syncthreads();
    if (threadIdx.x == 0) {
        float v = 0.f;
        #pragma unroll
        for (int i = 0; i < 8; i++) v += red[i];
        out[b] = v + fc_b[0];
    }
}

// ---------------------------------------------------------------------------
extern "C" void kernel_launch(void* const* d_in, const int* in_sizes, int n_in,
                              void* d_out, int out_size)
{
    (void)in_sizes; (void)n_in; (void)out_size;
    const float* x      = (const float*)d_in[0];
    const float* w_ih0  = (const float*)d_in[1];
    const float* w_rest = (const float*)d_in[2];
    const float* w_hh   = (const float*)d_in[3];
    const float* b_ih   = (const float*)d_in[4];
    const float* b_hh   = (const float*)d_in[5];
    const float* fc_w   = (const float*)d_in[6];
    const float* fc_b   = (const float*)d_in[7];
    float* out = (float*)d_out;

    const int lstm_smem = LSTM_WORDS * 4;                    // 205,888 B
    static bool attr_set = false;
    if (!attr_set) {
        cudaFuncSetAttribute(lstm_layer_kernel<true>,
                             cudaFuncAttributeMaxDynamicSharedMemorySize, lstm_smem);
        cudaFuncSetAttribute(lstm_layer_kernel<false>,
                             cudaFuncAttributeMaxDynamicSharedMemorySize, lstm_smem);
        attr_set = true;
    }

    const int half_l0 = (TSTEPS * BATCH * GDIM) / 2;

    reset_kernel<<<1, NFLAG * 32>>>();                                   // 0
    zeroh_kernel<<<(BATCH * HDIM / 2) / 256, 256>>>();                   // 1
    cvt_wih_kernel<<<(int)(((size_t)(NLAYERS - 1) * GDIM * HDIM / 2) / 256), 256>>>(w_rest); // 2
    layer0_xp_kernel<<<half_l0 / 256, 256>>>(x, w_ih0, 0);               // 3
    layer0_xp_kernel<<<half_l0 / 256, 256>>>(x, w_ih0, half_l0);         // 4

    for (int l = 0; l < NLAYERS; l++) {
        if (l < NLAYERS - 1) {
            lstm_layer_kernel<true><<<128, 288, lstm_smem>>>(            // lstm0 at slot 5
                w_hh + (size_t)l * GDIM * HDIM, l * TSTEPS, l,
                b_ih + (size_t)l * GDIM, b_hh + (size_t)l * GDIM);
        } else {
            lstm_layer_kernel<false><<<128, 288, lstm_smem>>>(
                w_hh + (size_t)l * GDIM * HDIM, l * TSTEPS, 0,
                b_ih + (size_t)l * GDIM, b_hh + (size_t)l * GDIM);
        }
    }

    fc_kernel<<<BATCH, 256>>>(fc_w, fc_b, out);
}